// round 1
// baseline (speedup 1.0000x reference)
#include <cuda_runtime.h>
#include <math.h>

#define BB 32
#define PP 1024
#define NN 1024
#define EE 128
#define HQd 128

// ---------------- scratch (static __device__, no allocations) ----------------
__device__ float g_ekk[BB * NN * 256];      // [b,n, 0:128)=exp(k)*v, [128:256)=exp(k)
__device__ float g_numden[BB * PP * 256];   // [b,p, 0:128)=num, [128:256)=den
__device__ float g_sigq[BB * PP * HQd];     // sigmoid(q)
__device__ float g_rowsum[BB * PP];         // softmax denominators

// fast helpers (accuracy ~1e-6 rel, far below 1e-3 budget)
__device__ __forceinline__ float fexp(float x) { return __expf(x); }
__device__ __forceinline__ float ftanh(float x) {
    // 1 - 2/(e^{2x}+1); saturates correctly for large |x|
    return 1.0f - 2.0f / (__expf(2.0f * x) + 1.0f);
}

// ---------------- kernel 0: zero row sums ----------------
__global__ void zero_rowsum_kernel() {
    int i = blockIdx.x * blockDim.x + threadIdx.x;
    if (i < BB * PP) g_rowsum[i] = 0.0f;
}

// ---------------- kernel 1: ek / ek*v  ([32768,128] @ [128,256]) ----------------
// 512 blocks x 256 threads, M_tile=64, N_tile=256, 8x8 micro tile.
__global__ void __launch_bounds__(256) kv_kernel(const float* __restrict__ enc,
                                                 const float* __restrict__ Wk,
                                                 const float* __restrict__ Wv) {
    extern __shared__ float sm[];
    float* Ws = sm;                 // [128][256]
    float* As = sm + 128 * 256;     // [64][128]
    const int tid = threadIdx.x;
    const int r0 = blockIdx.x * 64;

    float4* Ws4 = (float4*)Ws;
    const float4* Wk4 = (const float4*)Wk;
    const float4* Wv4 = (const float4*)Wv;
    for (int i = tid; i < 128 * 32; i += 256) {
        int k = i >> 5, c4 = i & 31;
        Ws4[k * 64 + c4]      = Wk4[k * 32 + c4];
        Ws4[k * 64 + 32 + c4] = Wv4[k * 32 + c4];
    }
    float4* As4 = (float4*)As;
    const float4* enc4 = (const float4*)enc;
    for (int i = tid; i < 64 * 32; i += 256) {
        int r = i >> 5, kq = i & 31;
        As4[r * 32 + kq] = enc4[(r0 + r) * 32 + kq];
    }
    __syncthreads();

    const int row_base = (tid >> 5) * 8;
    const int col_base = tid & 31;
    float acc[8][8];
#pragma unroll
    for (int r = 0; r < 8; r++)
#pragma unroll
        for (int i = 0; i < 8; i++) acc[r][i] = 0.0f;

    for (int k = 0; k < 128; k++) {
        float a[8], w[8];
#pragma unroll
        for (int r = 0; r < 8; r++) a[r] = As[(row_base + r) * 128 + k];
#pragma unroll
        for (int i = 0; i < 8; i++) w[i] = Ws[k * 256 + col_base + 32 * i];
#pragma unroll
        for (int r = 0; r < 8; r++)
#pragma unroll
            for (int i = 0; i < 8; i++) acc[r][i] = fmaf(a[r], w[i], acc[r][i]);
    }

#pragma unroll
    for (int r = 0; r < 8; r++) {
        int row = r0 + row_base + r;
#pragma unroll
        for (int i = 0; i < 4; i++) {
            float kk = acc[r][i];      // cols 0..127 -> k
            float vv = acc[r][i + 4];  // cols 128..255 -> v
            float ek = fexp(kk);
            int c = col_base + 32 * i;
            g_ekk[row * 256 + c]       = ek * vv;
            g_ekk[row * 256 + c + 128] = ek;
        }
    }
}

// ---------------- kernel 2: sigmoid(q1+q2+q_last) ----------------
// 512 blocks x 256 threads, M_tile=64, N_tile=128, 8x4 micro tile, 3 K phases.
__global__ void __launch_bounds__(256) q_kernel(const float* __restrict__ q1,
                                                const float* __restrict__ q2,
                                                const float* __restrict__ lastn,
                                                const float* __restrict__ loadv,
                                                const float* __restrict__ leftv,
                                                const float* __restrict__ Wq1,
                                                const float* __restrict__ Wq2,
                                                const float* __restrict__ Wql) {
    extern __shared__ float sm[];
    float* Ws = sm;                 // [128][128]
    float* As = sm + 128 * 128;     // [64][128]
    const int tid = threadIdx.x;
    const int r0 = blockIdx.x * 64;
    const int row_base = (tid >> 5) * 8;
    const int col_base = tid & 31;

    float acc[8][4];
#pragma unroll
    for (int r = 0; r < 8; r++)
#pragma unroll
        for (int i = 0; i < 4; i++) acc[r][i] = 0.0f;

    const float* Asrc[3] = {q1, q2, lastn};
    const float* Wsrc[3] = {Wq1, Wq2, Wql};

    for (int ph = 0; ph < 3; ph++) {
        __syncthreads();
        const float4* A4 = (const float4*)Asrc[ph];
        const float4* W4 = (const float4*)Wsrc[ph];
        float4* Ws4 = (float4*)Ws;
        float4* As4 = (float4*)As;
        for (int i = tid; i < 128 * 32; i += 256) Ws4[i] = W4[i];
        for (int i = tid; i < 64 * 32; i += 256) {
            int r = i >> 5, kq = i & 31;
            As4[r * 32 + kq] = A4[(r0 + r) * 32 + kq];
        }
        __syncthreads();
        for (int k = 0; k < 128; k++) {
            float a[8], w[4];
#pragma unroll
            for (int r = 0; r < 8; r++) a[r] = As[(row_base + r) * 128 + k];
#pragma unroll
            for (int i = 0; i < 4; i++) w[i] = Ws[k * 128 + col_base + 32 * i];
#pragma unroll
            for (int r = 0; r < 8; r++)
#pragma unroll
                for (int i = 0; i < 4; i++) acc[r][i] = fmaf(a[r], w[i], acc[r][i]);
        }
    }

#pragma unroll
    for (int r = 0; r < 8; r++) {
        int row = r0 + row_base + r;
        float lo = loadv[row];
        float le = leftv[row];
#pragma unroll
        for (int i = 0; i < 4; i++) {
            int c = col_base + 32 * i;
            float qv = acc[r][i] + lo * Wql[128 * 128 + c] + le * Wql[129 * 128 + c];
            g_sigq[row * 128 + c] = 1.0f / (1.0f + fexp(-qv));
        }
    }
}

// ---------------- kernel 3: num/den GEMM ----------------
// per batch: [1024,1024] @ [1024,256], A = exp(ninf - c1*cur_dist) on the fly.
// grid (16,32), 256 threads, M_tile=64, N_tile=256, K chunk 32, 8x8 micro.
__global__ void __launch_bounds__(256) b_kernel(const float* __restrict__ cur,
                                                const float* __restrict__ ninf,
                                                const float* __restrict__ lsp,
                                                const float* __restrict__ aalpha) {
    __shared__ float Ae[64 * 32];
    __shared__ float Bs[32 * 256];
    const int b = blockIdx.y;
    const int p0 = blockIdx.x * 64;
    const int tid = threadIdx.x;
    const float c1 = lsp[0] * aalpha[0];
    const int row_base = (tid >> 5) * 8;
    const int col_base = tid & 31;

    float acc[8][8];
#pragma unroll
    for (int r = 0; r < 8; r++)
#pragma unroll
        for (int i = 0; i < 8; i++) acc[r][i] = 0.0f;

    const float4* cur4 = (const float4*)cur;
    const float4* ninf4 = (const float4*)ninf;
    const float4* ekk4 = (const float4*)g_ekk;
    float4* Ae4 = (float4*)Ae;
    float4* Bs4 = (float4*)Bs;

    for (int k0 = 0; k0 < NN; k0 += 32) {
        __syncthreads();
        // A tile: 64 p-rows x 32 n-cols, e_bias computed at load
        for (int i = tid; i < 64 * 8; i += 256) {
            int r = i >> 3, kq = i & 7;
            int gi = (b * PP + p0 + r) * (NN / 4) + (k0 >> 2) + kq;
            float4 cd = cur4[gi];
            float4 nf = ninf4[gi];
            float4 e;
            e.x = fexp(nf.x - c1 * cd.x);
            e.y = fexp(nf.y - c1 * cd.y);
            e.z = fexp(nf.z - c1 * cd.z);
            e.w = fexp(nf.w - c1 * cd.w);
            Ae4[r * 8 + kq] = e;
        }
        // B tile: 32 n-rows x 256 cols of [ekv | ek]
        for (int i = tid; i < 32 * 64; i += 256) {
            int kk = i >> 6, cq = i & 63;
            Bs4[kk * 64 + cq] = ekk4[(b * NN + k0 + kk) * 64 + cq];
        }
        __syncthreads();
#pragma unroll
        for (int k = 0; k < 32; k++) {
            float a[8], w[8];
#pragma unroll
            for (int r = 0; r < 8; r++) a[r] = Ae[(row_base + r) * 32 + k];
#pragma unroll
            for (int i = 0; i < 8; i++) w[i] = Bs[k * 256 + col_base + 32 * i];
#pragma unroll
            for (int r = 0; r < 8; r++)
#pragma unroll
                for (int i = 0; i < 8; i++) acc[r][i] = fmaf(a[r], w[i], acc[r][i]);
        }
    }

#pragma unroll
    for (int r = 0; r < 8; r++) {
        int row = b * PP + p0 + row_base + r;
#pragma unroll
        for (int i = 0; i < 8; i++)
            g_numden[row * 256 + col_base + 32 * i] = acc[r][i];
    }
}

// ---------------- kernel 4: score GEMM + tanh/clip/exp + row-sum ----------------
// per batch: [1024,128] (AFT, built on the fly) x enc^T -> [1024,1024]
// grid (8,8,32): x=p-tile(128), y=n-tile(128), z=b. 256 threads, 8x8 micro.
__global__ void __launch_bounds__(256) c_kernel(const float* __restrict__ enc,
                                                const float* __restrict__ cur,
                                                const float* __restrict__ ninf,
                                                const float* __restrict__ lsp,
                                                const float* __restrict__ palpha,
                                                float* __restrict__ out) {
    __shared__ float Aft[128 * 33];
    __shared__ float En[128 * 33];
    const int p0 = blockIdx.x * 128;
    const int n0 = blockIdx.y * 128;
    const int b = blockIdx.z;
    const int tid = threadIdx.x;
    const int row_base = (tid >> 4) * 8;  // 16 groups of 8 rows
    const int col_base = tid & 15;        // cols col_base + 16*i

    float acc[8][8];
#pragma unroll
    for (int r = 0; r < 8; r++)
#pragma unroll
        for (int i = 0; i < 8; i++) acc[r][i] = 0.0f;

    const float4* nd4 = (const float4*)g_numden;
    const float4* sq4 = (const float4*)g_sigq;
    const float4* enc4 = (const float4*)enc;

    for (int k0 = 0; k0 < 128; k0 += 32) {
        __syncthreads();
        // AFT tile: 128 rows x 32 d  (sigmoid_q * num/den)
        for (int i = tid; i < 128 * 8; i += 256) {
            int r = i >> 3, dq = i & 7;
            int row = b * PP + p0 + r;
            float4 num = nd4[row * 64 + (k0 >> 2) + dq];
            float4 den = nd4[row * 64 + 32 + (k0 >> 2) + dq];
            float4 sq = sq4[row * 32 + (k0 >> 2) + dq];
            int base = r * 33 + dq * 4;
            Aft[base + 0] = sq.x * num.x / (den.x + 1e-20f);
            Aft[base + 1] = sq.y * num.y / (den.y + 1e-20f);
            Aft[base + 2] = sq.z * num.z / (den.z + 1e-20f);
            Aft[base + 3] = sq.w * num.w / (den.w + 1e-20f);
        }
        // enc tile: 128 n x 32 d
        for (int i = tid; i < 128 * 8; i += 256) {
            int n = i >> 3, dq = i & 7;
            float4 v = enc4[(b * NN + n0 + n) * 32 + (k0 >> 2) + dq];
            int base = n * 33 + dq * 4;
            En[base + 0] = v.x;
            En[base + 1] = v.y;
            En[base + 2] = v.z;
            En[base + 3] = v.w;
        }
        __syncthreads();
#pragma unroll
        for (int k = 0; k < 32; k++) {
            float a[8], w[8];
#pragma unroll
            for (int r = 0; r < 8; r++) a[r] = Aft[(row_base + r) * 33 + k];
#pragma unroll
            for (int i = 0; i < 8; i++) w[i] = En[(col_base + 16 * i) * 33 + k];
#pragma unroll
            for (int r = 0; r < 8; r++)
#pragma unroll
                for (int i = 0; i < 8; i++) acc[r][i] = fmaf(a[r], w[i], acc[r][i]);
        }
    }

    // epilogue: scaled score -> 10*tanh -> +ninf -> exp(.-10), row partial sums
    const float c2 = lsp[0] * palpha[0];
    const float inv_sqrt_e = 1.0f / 11.313708498984761f;
#pragma unroll
    for (int r = 0; r < 8; r++) {
        int p = p0 + row_base + r;
        float part = 0.0f;
#pragma unroll
        for (int i = 0; i < 8; i++) {
            int n = n0 + col_base + 16 * i;
            int gi = (b * PP + p) * NN + n;
            float cd = cur[gi];
            float nf = ninf[gi];
            float s = acc[r][i] * inv_sqrt_e - c2 * cd;
            float cs = 10.0f * ftanh(s);
            float es = fexp(cs + nf - 10.0f);  // clipped <= 10, so max-shift 10 is safe
            out[gi] = es;
            part += es;
        }
        // reduce over the 16 lanes that share this row (xor stays in 16-lane half)
        part += __shfl_xor_sync(0xffffffffu, part, 8);
        part += __shfl_xor_sync(0xffffffffu, part, 4);
        part += __shfl_xor_sync(0xffffffffu, part, 2);
        part += __shfl_xor_sync(0xffffffffu, part, 1);
        if (col_base == 0) atomicAdd(&g_rowsum[b * PP + p], part);
    }
}

// ---------------- kernel 5: normalize ----------------
__global__ void norm_kernel(float* __restrict__ out) {
    int i = blockIdx.x * blockDim.x + threadIdx.x;  // float4 index
    float4* o4 = (float4*)out;
    float4 v = o4[i];
    float inv = 1.0f / g_rowsum[i >> 8];  // 256 float4 per row of 1024
    v.x *= inv;
    v.y *= inv;
    v.z *= inv;
    v.w *= inv;
    o4[i] = v;
}

// ---------------- launch ----------------
extern "C" void kernel_launch(void* const* d_in, const int* in_sizes, int n_in,
                              void* d_out, int out_size) {
    (void)in_sizes; (void)n_in; (void)out_size;
    const float* enc    = (const float*)d_in[0];
    const float* q1     = (const float*)d_in[1];
    const float* q2     = (const float*)d_in[2];
    const float* lastn  = (const float*)d_in[3];
    const float* loadv  = (const float*)d_in[4];
    const float* leftv  = (const float*)d_in[5];
    const float* cur    = (const float*)d_in[6];
    const float* ls     = (const float*)d_in[7];
    const float* ninf   = (const float*)d_in[8];
    const float* Wq1    = (const float*)d_in[9];
    const float* Wq2    = (const float*)d_in[10];
    const float* Wql    = (const float*)d_in[11];
    const float* Wk     = (const float*)d_in[12];
    const float* Wv     = (const float*)d_in[13];
    const float* aalpha = (const float*)d_in[14];
    const float* palpha = (const float*)d_in[15];
    float* out = (float*)d_out;

    cudaFuncSetAttribute(kv_kernel, cudaFuncAttributeMaxDynamicSharedMemorySize, 163840);
    cudaFuncSetAttribute(q_kernel, cudaFuncAttributeMaxDynamicSharedMemorySize, 98304);

    zero_rowsum_kernel<<<32, 1024>>>();
    kv_kernel<<<512, 256, 163840>>>(enc, Wk, Wv);
    q_kernel<<<512, 256, 98304>>>(q1, q2, lastn, loadv, leftv, Wq1, Wq2, Wql);
    b_kernel<<<dim3(16, 32), 256>>>(cur, ninf, ls, aalpha);
    c_kernel<<<dim3(8, 8, 32), 256>>>(enc, cur, ninf, ls, palpha, out);
    norm_kernel<<<32768, 256>>>(out);
}

// round 3
// speedup vs baseline: 1.5093x; 1.5093x over previous
#include <cuda_runtime.h>
#include <math.h>
#include <stdint.h>

#define BB 32
#define PP 1024
#define NN 1024

typedef unsigned long long u64;
typedef unsigned int u32;

// ---------------- scratch (static __device__, no allocations) ----------------
__device__ float g_ekk[BB * NN * 256];     // [b,n, 0:128)=exp(k)*v, [128:256)=exp(k)
__device__ float g_numden[BB * PP * 256];  // [b,p, 0:128)=num, [128:256)=den
__device__ float g_sigq[BB * PP * 128];    // sigmoid(q)
__device__ float g_aftT[BB * 128 * PP];    // AFT transposed: [b][d][p]
__device__ float g_encT[BB * 128 * NN];    // enc transposed: [b][d][n]
__device__ float g_rowsum[BB * PP];        // softmax denominators

// ---------------- helpers ----------------
__device__ __forceinline__ float fexp(float x) { return __expf(x); }
__device__ __forceinline__ float ftanh(float x) {
    return 1.0f - 2.0f / (__expf(2.0f * x) + 1.0f);
}
__device__ __forceinline__ void ffma2(u64& acc, u64 a, u64 b) {
    asm("fma.rn.f32x2 %0, %1, %2, %0;" : "+l"(acc) : "l"(a), "l"(b));
}
__device__ __forceinline__ u64 dup2(float x) {
    u64 r; asm("mov.b64 %0, {%1, %1};" : "=l"(r) : "f"(x)); return r;
}
__device__ __forceinline__ float2 unpack2(u64 v) {
    float2 r; asm("mov.b64 {%0, %1}, %2;" : "=f"(r.x), "=f"(r.y) : "l"(v)); return r;
}
__device__ __forceinline__ void cp16(void* smem_dst, const void* gmem_src) {
    u32 s = (u32)__cvta_generic_to_shared(smem_dst);
    asm volatile("cp.async.cg.shared.global [%0], [%1], 16;" :: "r"(s), "l"(gmem_src));
}
__device__ __forceinline__ void cp_commit() { asm volatile("cp.async.commit_group;"); }
__device__ __forceinline__ void cp_wait0() { asm volatile("cp.async.wait_group 0;" ::: "memory"); }

// ---------------- kernel 0: zero row sums ----------------
__global__ void zero_rowsum_kernel() {
    int i = blockIdx.x * blockDim.x + threadIdx.x;
    if (i < BB * PP) g_rowsum[i] = 0.0f;
}

// ---------------- kernel 1: ek / ek*v  ([32768,128] @ [128,256]) ----------------
// grid 512, 256 thr. A transposed in smem, W double-buffered via cp.async.
__global__ void __launch_bounds__(256, 2) kv_kernel(const float* __restrict__ enc,
                                                    const float* __restrict__ Wk,
                                                    const float* __restrict__ Wv) {
    extern __shared__ float sm[];
    float* At  = sm;              // [128][64] transposed A
    float* Ws0 = sm + 128 * 64;   // [32][256]
    float* Ws1 = Ws0 + 32 * 256;
    const int tid = threadIdx.x;
    const int r0 = blockIdx.x * 64;

    // fill At (transpose enc tile)
    {
        int r = tid >> 2;
        int c0 = (tid & 3) * 32;
        const float4* e4 = (const float4*)(enc + (size_t)(r0 + r) * 128 + c0);
#pragma unroll
        for (int q = 0; q < 8; q++) {
            float4 v = e4[q];
            int k = c0 + q * 4;
            At[(k + 0) * 64 + r] = v.x;
            At[(k + 1) * 64 + r] = v.y;
            At[(k + 2) * 64 + r] = v.z;
            At[(k + 3) * 64 + r] = v.w;
        }
    }
    // W chunk fill (cp.async): cols [0,128)=Wk, [128,256)=Wv
#define FILL_W(dst, k0)                                                           \
    {                                                                              \
        _Pragma("unroll")                                                          \
        for (int t = 0; t < 8; t++) {                                              \
            int l = tid + 256 * t;                                                 \
            int k = l >> 6, c16 = l & 63;                                          \
            const float* src = (c16 < 32) ? (Wk + ((k0) + k) * 128 + c16 * 4)      \
                                          : (Wv + ((k0) + k) * 128 + (c16 - 32) * 4); \
            cp16((dst) + k * 256 + c16 * 4, src);                                  \
        }                                                                          \
    }
    FILL_W(Ws0, 0);
    cp_commit(); cp_wait0();
    __syncthreads();

    const int rb = (tid >> 5) * 8;
    const int cb = (tid & 31) * 4;     // cols cb..cb+3 (k part) and cb+128.. (v part)
    u64 acc[4][8] = {};

    for (int ch = 0; ch < 4; ch++) {
        float* Wc = (ch & 1) ? Ws1 : Ws0;
        float* Wn = (ch & 1) ? Ws0 : Ws1;
        if (ch < 3) { FILL_W(Wn, (ch + 1) * 32); cp_commit(); }
        int k0 = ch * 32;
#pragma unroll
        for (int k = 0; k < 32; k++) {
            const float* ar = At + (k0 + k) * 64 + rb;
            u64 a0 = *(const u64*)(ar + 0);
            u64 a1 = *(const u64*)(ar + 2);
            u64 a2 = *(const u64*)(ar + 4);
            u64 a3 = *(const u64*)(ar + 6);
            float4 wk4 = *(const float4*)(Wc + k * 256 + cb);
            float4 wv4 = *(const float4*)(Wc + k * 256 + cb + 128);
            float w[8] = {wk4.x, wk4.y, wk4.z, wk4.w, wv4.x, wv4.y, wv4.z, wv4.w};
#pragma unroll
            for (int j = 0; j < 8; j++) {
                u64 wd = dup2(w[j]);
                ffma2(acc[0][j], a0, wd);
                ffma2(acc[1][j], a1, wd);
                ffma2(acc[2][j], a2, wd);
                ffma2(acc[3][j], a3, wd);
            }
        }
        if (ch < 3) cp_wait0();
        __syncthreads();
    }
#undef FILL_W

#pragma unroll
    for (int t = 0; t < 4; t++) {
        int row = r0 + rb + 2 * t;
#pragma unroll
        for (int j = 0; j < 4; j++) {
            float2 pk = unpack2(acc[t][j]);
            float2 pv = unpack2(acc[t][j + 4]);
            int c = cb + j;
            float e0 = fexp(pk.x), e1 = fexp(pk.y);
            g_ekk[(size_t)row * 256 + c]             = e0 * pv.x;
            g_ekk[(size_t)row * 256 + c + 128]       = e0;
            g_ekk[(size_t)(row + 1) * 256 + c]       = e1 * pv.y;
            g_ekk[(size_t)(row + 1) * 256 + c + 128] = e1;
        }
    }
}

// ---------------- kernel 2: sigmoid(q1+q2+q_last) ----------------
__global__ void __launch_bounds__(256, 2) q_kernel(const float* __restrict__ q1,
                                                   const float* __restrict__ q2,
                                                   const float* __restrict__ lastn,
                                                   const float* __restrict__ loadv,
                                                   const float* __restrict__ leftv,
                                                   const float* __restrict__ Wq1,
                                                   const float* __restrict__ Wq2,
                                                   const float* __restrict__ Wql) {
    extern __shared__ float sm[];
    float* At = sm;            // [128][64]
    float* Ws = sm + 128 * 64; // [128][128]
    const int tid = threadIdx.x;
    const int r0 = blockIdx.x * 64;
    const int rb = (tid >> 5) * 8;
    const int cb = (tid & 31) * 4;

    u64 acc[4][4] = {};
    const float* Asrc[3] = {q1, q2, lastn};
    const float* Wsrc[3] = {Wq1, Wq2, Wql};

    for (int ph = 0; ph < 3; ph++) {
        __syncthreads();
        {
            int r = tid >> 2;
            int c0 = (tid & 3) * 32;
            const float4* a4 = (const float4*)(Asrc[ph] + (size_t)(r0 + r) * 128 + c0);
#pragma unroll
            for (int q = 0; q < 8; q++) {
                float4 v = a4[q];
                int k = c0 + q * 4;
                At[(k + 0) * 64 + r] = v.x;
                At[(k + 1) * 64 + r] = v.y;
                At[(k + 2) * 64 + r] = v.z;
                At[(k + 3) * 64 + r] = v.w;
            }
            const float4* W4 = (const float4*)Wsrc[ph];
            float4* Ws4 = (float4*)Ws;
            for (int i = tid; i < 128 * 32; i += 256) Ws4[i] = W4[i];
        }
        __syncthreads();
#pragma unroll 8
        for (int k = 0; k < 128; k++) {
            const float* ar = At + k * 64 + rb;
            u64 a0 = *(const u64*)(ar + 0);
            u64 a1 = *(const u64*)(ar + 2);
            u64 a2 = *(const u64*)(ar + 4);
            u64 a3 = *(const u64*)(ar + 6);
            float4 w4 = *(const float4*)(Ws + k * 128 + cb);
            float w[4] = {w4.x, w4.y, w4.z, w4.w};
#pragma unroll
            for (int j = 0; j < 4; j++) {
                u64 wd = dup2(w[j]);
                ffma2(acc[0][j], a0, wd);
                ffma2(acc[1][j], a1, wd);
                ffma2(acc[2][j], a2, wd);
                ffma2(acc[3][j], a3, wd);
            }
        }
    }

#pragma unroll
    for (int t = 0; t < 4; t++) {
        int row = r0 + rb + 2 * t;
        float lo0 = loadv[row], le0 = leftv[row];
        float lo1 = loadv[row + 1], le1 = leftv[row + 1];
#pragma unroll
        for (int j = 0; j < 4; j++) {
            int c = cb + j;
            float2 p = unpack2(acc[t][j]);
            float wl = Wql[128 * 128 + c];
            float we = Wql[129 * 128 + c];
            float v0 = p.x + lo0 * wl + le0 * we;
            float v1 = p.y + lo1 * wl + le1 * we;
            g_sigq[(size_t)row * 128 + c]       = 1.0f / (1.0f + fexp(-v0));
            g_sigq[(size_t)(row + 1) * 128 + c] = 1.0f / (1.0f + fexp(-v1));
        }
    }
}

// ---------------- kernel 3: num/den GEMM ----------------
// per batch: [1024,1024] @ [1024,256]; A = exp(ninf - c1*cur) built on the fly.
// grid (16,32), 256 thr. A reg-staged + transposed STS; B via cp.async. Ping-pong.
__global__ void __launch_bounds__(256, 2) b_kernel(const float* __restrict__ cur,
                                                   const float* __restrict__ ninf,
                                                   const float* __restrict__ lsp,
                                                   const float* __restrict__ aalpha) {
    extern __shared__ float sm[];
    float* At0 = sm;                 // [32][64]
    float* At1 = sm + 2048;
    float* Bs0 = sm + 4096;          // [32][256]
    float* Bs1 = sm + 4096 + 8192;
    const int tid = threadIdx.x;
    const int b = blockIdx.y;
    const int p0 = blockIdx.x * 64;
    const float c1 = lsp[0] * aalpha[0];

    const int rA = tid >> 2;          // 0..63
    const int kqA = (tid & 3) * 8;    // 0,8,16,24
    const float4* cur4 = (const float4*)cur;
    const float4* ninf4 = (const float4*)ninf;
    const size_t arow = (size_t)(b * PP + p0 + rA) * 256;  // float4 units per row = 256

    float4 cd0, cd1, nf0, nf1;
#define LD_A(k0)                                      \
    {                                                 \
        size_t gi = arow + ((k0) + kqA) / 4;          \
        cd0 = cur4[gi]; cd1 = cur4[gi + 1];           \
        nf0 = ninf4[gi]; nf1 = ninf4[gi + 1];         \
    }
#define ST_A(dst)                                                         \
    {                                                                     \
        float e[8];                                                       \
        e[0] = fexp(nf0.x - c1 * cd0.x); e[1] = fexp(nf0.y - c1 * cd0.y); \
        e[2] = fexp(nf0.z - c1 * cd0.z); e[3] = fexp(nf0.w - c1 * cd0.w); \
        e[4] = fexp(nf1.x - c1 * cd1.x); e[5] = fexp(nf1.y - c1 * cd1.y); \
        e[6] = fexp(nf1.z - c1 * cd1.z); e[7] = fexp(nf1.w - c1 * cd1.w); \
        _Pragma("unroll")                                                 \
        for (int j = 0; j < 8; j++) (dst)[(kqA + j) * 64 + rA] = e[j];    \
    }
#define FILL_B(dst, k0)                                                        \
    {                                                                          \
        _Pragma("unroll")                                                      \
        for (int t = 0; t < 8; t++) {                                          \
            int l = tid + 256 * t;                                             \
            int k = l >> 6, c16 = l & 63;                                      \
            cp16((dst) + k * 256 + c16 * 4,                                    \
                 g_ekk + (size_t)(b * NN + (k0) + k) * 256 + c16 * 4);         \
        }                                                                      \
    }

    LD_A(0); ST_A(At0);
    FILL_B(Bs0, 0);
    cp_commit(); cp_wait0();
    __syncthreads();

    const int rb = (tid >> 5) * 8;
    const int cb = (tid & 31) * 8;
    u64 acc[4][8] = {};

    for (int ch = 0; ch < 32; ch++) {
        float* At = (ch & 1) ? At1 : At0;
        float* Bs = (ch & 1) ? Bs1 : Bs0;
        float* Atn = (ch & 1) ? At0 : At1;
        float* Bsn = (ch & 1) ? Bs0 : Bs1;
        if (ch < 31) {
            LD_A((ch + 1) * 32);
            FILL_B(Bsn, (ch + 1) * 32);
            cp_commit();
        }
#pragma unroll
        for (int k = 0; k < 32; k++) {
            const float* ar = At + k * 64 + rb;
            u64 a0 = *(const u64*)(ar + 0);
            u64 a1 = *(const u64*)(ar + 2);
            u64 a2 = *(const u64*)(ar + 4);
            u64 a3 = *(const u64*)(ar + 6);
            float4 wA = *(const float4*)(Bs + k * 256 + cb);
            float4 wB = *(const float4*)(Bs + k * 256 + cb + 4);
            float w[8] = {wA.x, wA.y, wA.z, wA.w, wB.x, wB.y, wB.z, wB.w};
#pragma unroll
            for (int j = 0; j < 8; j++) {
                u64 wd = dup2(w[j]);
                ffma2(acc[0][j], a0, wd);
                ffma2(acc[1][j], a1, wd);
                ffma2(acc[2][j], a2, wd);
                ffma2(acc[3][j], a3, wd);
            }
        }
        if (ch < 31) { ST_A(Atn); cp_wait0(); }
        __syncthreads();
    }
#undef LD_A
#undef ST_A
#undef FILL_B

#pragma unroll
    for (int t = 0; t < 4; t++) {
        size_t row = (size_t)(b * PP + p0 + rb + 2 * t);
        float2 p[8];
#pragma unroll
        for (int j = 0; j < 8; j++) p[j] = unpack2(acc[t][j]);
        *(float4*)(g_numden + row * 256 + cb)           = make_float4(p[0].x, p[1].x, p[2].x, p[3].x);
        *(float4*)(g_numden + row * 256 + cb + 4)       = make_float4(p[4].x, p[5].x, p[6].x, p[7].x);
        *(float4*)(g_numden + (row + 1) * 256 + cb)     = make_float4(p[0].y, p[1].y, p[2].y, p[3].y);
        *(float4*)(g_numden + (row + 1) * 256 + cb + 4) = make_float4(p[4].y, p[5].y, p[6].y, p[7].y);
    }
}

// ---------------- transpose kernels ----------------
// AFT^T: g_aftT[b][d][p] = sigq*num/den   (from g_numden/g_sigq)
__global__ void aftT_kernel() {
    __shared__ float t[32][33];
    const int r0 = blockIdx.x * 32;
    const int d0 = blockIdx.y * 32;
    const int b = blockIdx.z;
    const int tx = threadIdx.x, ty = threadIdx.y;
#pragma unroll
    for (int i = 0; i < 4; i++) {
        int row = r0 + ty + i * 8;
        size_t base = (size_t)(b * PP + row);
        float num = g_numden[base * 256 + d0 + tx];
        float den = g_numden[base * 256 + 128 + d0 + tx];
        float s   = g_sigq[base * 128 + d0 + tx];
        t[ty + i * 8][tx] = s * num / (den + 1e-20f);
    }
    __syncthreads();
#pragma unroll
    for (int i = 0; i < 4; i++) {
        int d = d0 + ty + i * 8;
        g_aftT[(size_t)(b * 128 + d) * PP + r0 + tx] = t[tx][ty + i * 8];
    }
}

// enc^T: g_encT[b][d][n]
__global__ void encT_kernel(const float* __restrict__ enc) {
    __shared__ float t[32][33];
    const int r0 = blockIdx.x * 32;
    const int d0 = blockIdx.y * 32;
    const int b = blockIdx.z;
    const int tx = threadIdx.x, ty = threadIdx.y;
#pragma unroll
    for (int i = 0; i < 4; i++) {
        int row = r0 + ty + i * 8;
        t[ty + i * 8][tx] = enc[(size_t)(b * NN + row) * 128 + d0 + tx];
    }
    __syncthreads();
#pragma unroll
    for (int i = 0; i < 4; i++) {
        int d = d0 + ty + i * 8;
        g_encT[(size_t)(b * 128 + d) * NN + r0 + tx] = t[tx][ty + i * 8];
    }
}

// ---------------- kernel 4: score GEMM + tanh/clip/exp + row-sum ----------------
// per batch: AFT[1024,128] @ enc^T -> [1024,1024]. grid (8,8,32), 256 thr.
__global__ void __launch_bounds__(256, 2) c_kernel(const float* __restrict__ cur,
                                                   const float* __restrict__ ninf,
                                                   const float* __restrict__ lsp,
                                                   const float* __restrict__ palpha,
                                                   float* __restrict__ out) {
    extern __shared__ float sm[];
    float* At0 = sm;           // [32][128]
    float* At1 = sm + 4096;
    float* Bt0 = sm + 8192;    // [32][128]
    float* Bt1 = sm + 12288;
    const int tid = threadIdx.x;
    const int p0 = blockIdx.x * 128;
    const int n0 = blockIdx.y * 128;
    const int b = blockIdx.z;

#define FILL_T(dst, src, off0, d0)                                            \
    {                                                                         \
        _Pragma("unroll")                                                     \
        for (int t = 0; t < 4; t++) {                                         \
            int l = tid + 256 * t;                                            \
            int k = l >> 5, c16 = l & 31;                                     \
            cp16((dst) + k * 128 + c16 * 4,                                   \
                 (src) + (size_t)(b * 128 + (d0) + k) * 1024 + (off0) + c16 * 4); \
        }                                                                     \
    }

    FILL_T(At0, g_aftT, p0, 0);
    FILL_T(Bt0, g_encT, n0, 0);
    cp_commit(); cp_wait0();
    __syncthreads();

    const int rb = (tid >> 4) * 8;   // 16 groups * 8 = 128 rows
    const int cb = (tid & 15) * 8;   // 16 groups * 8 = 128 cols
    u64 acc[4][8] = {};

    for (int ch = 0; ch < 4; ch++) {
        float* At = (ch & 1) ? At1 : At0;
        float* Bt = (ch & 1) ? Bt1 : Bt0;
        float* Atn = (ch & 1) ? At0 : At1;
        float* Btn = (ch & 1) ? Bt0 : Bt1;
        if (ch < 3) {
            FILL_T(Atn, g_aftT, p0, (ch + 1) * 32);
            FILL_T(Btn, g_encT, n0, (ch + 1) * 32);
            cp_commit();
        }
#pragma unroll
        for (int k = 0; k < 32; k++) {
            const float* ar = At + k * 128 + rb;
            u64 a0 = *(const u64*)(ar + 0);
            u64 a1 = *(const u64*)(ar + 2);
            u64 a2 = *(const u64*)(ar + 4);
            u64 a3 = *(const u64*)(ar + 6);
            float4 wA = *(const float4*)(Bt + k * 128 + cb);
            float4 wB = *(const float4*)(Bt + k * 128 + cb + 4);
            float w[8] = {wA.x, wA.y, wA.z, wA.w, wB.x, wB.y, wB.z, wB.w};
#pragma unroll
            for (int j = 0; j < 8; j++) {
                u64 wd = dup2(w[j]);
                ffma2(acc[0][j], a0, wd);
                ffma2(acc[1][j], a1, wd);
                ffma2(acc[2][j], a2, wd);
                ffma2(acc[3][j], a3, wd);
            }
        }
        if (ch < 3) cp_wait0();
        __syncthreads();
    }
#undef FILL_T

    // epilogue: score -> 10*tanh -> +ninf -> exp(.-10), partial row sums
    const float c2 = lsp[0] * palpha[0];
    const float inv_sqrt_e = 1.0f / 11.313708498984761f;
#pragma unroll
    for (int t = 0; t < 4; t++) {
        float2 p[8];
#pragma unroll
        for (int j = 0; j < 8; j++) p[j] = unpack2(acc[t][j]);
#pragma unroll
        for (int half = 0; half < 2; half++) {
            int prow = p0 + rb + 2 * t + half;
            size_t gi = (size_t)(b * PP + prow) * NN + n0 + cb;
            float4 cd0 = *(const float4*)(cur + gi);
            float4 cd1 = *(const float4*)(cur + gi + 4);
            float4 nf0 = *(const float4*)(ninf + gi);
            float4 nf1 = *(const float4*)(ninf + gi + 4);
            float cd[8] = {cd0.x, cd0.y, cd0.z, cd0.w, cd1.x, cd1.y, cd1.z, cd1.w};
            float nf[8] = {nf0.x, nf0.y, nf0.z, nf0.w, nf1.x, nf1.y, nf1.z, nf1.w};
            float es[8];
            float part = 0.0f;
#pragma unroll
            for (int j = 0; j < 8; j++) {
                float sc = half ? p[j].y : p[j].x;
                float s = sc * inv_sqrt_e - c2 * cd[j];
                float cs = 10.0f * ftanh(s);
                es[j] = fexp(cs + nf[j] - 10.0f);
                part += es[j];
            }
            *(float4*)(out + gi)     = make_float4(es[0], es[1], es[2], es[3]);
            *(float4*)(out + gi + 4) = make_float4(es[4], es[5], es[6], es[7]);
            part += __shfl_xor_sync(0xffffffffu, part, 8);
            part += __shfl_xor_sync(0xffffffffu, part, 4);
            part += __shfl_xor_sync(0xffffffffu, part, 2);
            part += __shfl_xor_sync(0xffffffffu, part, 1);
            if ((tid & 15) == 0) atomicAdd(&g_rowsum[b * PP + prow], part);
        }
    }
}

// ---------------- kernel 5: normalize ----------------
__global__ void norm_kernel(float* __restrict__ out) {
    int i = blockIdx.x * blockDim.x + threadIdx.x;  // float4 index
    float4* o4 = (float4*)out;
    float4 v = o4[i];
    float inv = 1.0f / g_rowsum[i >> 8];
    v.x *= inv; v.y *= inv; v.z *= inv; v.w *= inv;
    o4[i] = v;
}

// ---------------- launch ----------------
extern "C" void kernel_launch(void* const* d_in, const int* in_sizes, int n_in,
                              void* d_out, int out_size) {
    (void)in_sizes; (void)n_in; (void)out_size;
    const float* enc    = (const float*)d_in[0];
    const float* q1     = (const float*)d_in[1];
    const float* q2     = (const float*)d_in[2];
    const float* lastn  = (const float*)d_in[3];
    const float* loadv  = (const float*)d_in[4];
    const float* leftv  = (const float*)d_in[5];
    const float* cur    = (const float*)d_in[6];
    const float* ls     = (const float*)d_in[7];
    const float* ninf   = (const float*)d_in[8];
    const float* Wq1    = (const float*)d_in[9];
    const float* Wq2    = (const float*)d_in[10];
    const float* Wql    = (const float*)d_in[11];
    const float* Wk     = (const float*)d_in[12];
    const float* Wv     = (const float*)d_in[13];
    const float* aalpha = (const float*)d_in[14];
    const float* palpha = (const float*)d_in[15];
    float* out = (float*)d_out;

    cudaFuncSetAttribute(kv_kernel, cudaFuncAttributeMaxDynamicSharedMemorySize, 98304);
    cudaFuncSetAttribute(q_kernel, cudaFuncAttributeMaxDynamicSharedMemorySize, 98304);
    cudaFuncSetAttribute(b_kernel, cudaFuncAttributeMaxDynamicSharedMemorySize, 81920);
    cudaFuncSetAttribute(c_kernel, cudaFuncAttributeMaxDynamicSharedMemorySize, 65536);

    zero_rowsum_kernel<<<32, 1024>>>();
    encT_kernel<<<dim3(32, 4, 32), dim3(32, 8)>>>(enc);
    kv_kernel<<<512, 256, 98304>>>(enc, Wk, Wv);
    q_kernel<<<512, 256, 98304>>>(q1, q2, lastn, loadv, leftv, Wq1, Wq2, Wql);
    b_kernel<<<dim3(16, 32), 256, 81920>>>(cur, ninf, ls, aalpha);
    aftT_kernel<<<dim3(32, 4, 32), dim3(32, 8)>>>();
    c_kernel<<<dim3(8, 8, 32), 256, 65536>>>(cur, ninf, ls, palpha, out);
    norm_kernel<<<32768, 256>>>(out);
}

// round 4
// speedup vs baseline: 2.0993x; 1.3909x over previous
#include <cuda_runtime.h>
#include <cuda_bf16.h>
#include <math.h>
#include <stdint.h>

#define BB 32
#define PP 1024
#define NN 1024

typedef unsigned long long u64;
typedef unsigned int u32;

// ---------------- scratch (static __device__, no allocations) ----------------
__device__ float g_ekk[BB * NN * 256];     // [b,n, 0:128)=exp(k)*v, [128:256)=exp(k)
__device__ float g_numden[BB * PP * 256];  // [b,p, 0:128)=num, [128:256)=den
__device__ float g_sigq[BB * PP * 128];    // sigmoid(q)
__device__ float g_rowsum[BB * PP];        // softmax denominators
// bf16 split operands
__device__ __nv_bfloat16 g_ekkT_h[BB * 256 * NN];  // [b][c][n]
__device__ __nv_bfloat16 g_ekkT_l[BB * 256 * NN];
__device__ __nv_bfloat16 g_aft_h[BB * PP * 128];   // [b][p][d]
__device__ __nv_bfloat16 g_aft_l[BB * PP * 128];
__device__ __nv_bfloat16 g_enc_h[BB * NN * 128];   // [b][n][d]
__device__ __nv_bfloat16 g_enc_l[BB * NN * 128];

// ---------------- helpers ----------------
__device__ __forceinline__ float fexp(float x) { return __expf(x); }
__device__ __forceinline__ float ftanh(float x) {
    return 1.0f - 2.0f / (__expf(2.0f * x) + 1.0f);
}
__device__ __forceinline__ void ffma2(u64& acc, u64 a, u64 b) {
    asm("fma.rn.f32x2 %0, %1, %2, %0;" : "+l"(acc) : "l"(a), "l"(b));
}
__device__ __forceinline__ u64 dup2(float x) {
    u64 r; asm("mov.b64 %0, {%1, %1};" : "=l"(r) : "f"(x)); return r;
}
__device__ __forceinline__ float2 unpack2(u64 v) {
    float2 r; asm("mov.b64 {%0, %1}, %2;" : "=f"(r.x), "=f"(r.y) : "l"(v)); return r;
}
__device__ __forceinline__ void cp16(void* smem_dst, const void* gmem_src) {
    u32 s = (u32)__cvta_generic_to_shared(smem_dst);
    asm volatile("cp.async.cg.shared.global [%0], [%1], 16;" :: "r"(s), "l"(gmem_src));
}
__device__ __forceinline__ void cp_commit() { asm volatile("cp.async.commit_group;"); }
__device__ __forceinline__ void cp_wait0() { asm volatile("cp.async.wait_group 0;" ::: "memory"); }

__device__ __forceinline__ u32 smem_u32(const void* p) {
    return (u32)__cvta_generic_to_shared(p);
}
__device__ __forceinline__ void ldsm_x4(u32 addr, u32& r0, u32& r1, u32& r2, u32& r3) {
    asm volatile("ldmatrix.sync.aligned.m8n8.x4.shared.b16 {%0,%1,%2,%3}, [%4];"
                 : "=r"(r0), "=r"(r1), "=r"(r2), "=r"(r3) : "r"(addr));
}
__device__ __forceinline__ void mma_bf16(float* c, const u32* a, const u32* b) {
    asm volatile(
        "mma.sync.aligned.m16n8k16.row.col.f32.bf16.bf16.f32 "
        "{%0,%1,%2,%3}, {%4,%5,%6,%7}, {%8,%9}, {%0,%1,%2,%3};"
        : "+f"(c[0]), "+f"(c[1]), "+f"(c[2]), "+f"(c[3])
        : "r"(a[0]), "r"(a[1]), "r"(a[2]), "r"(a[3]), "r"(b[0]), "r"(b[1]));
}
__device__ __forceinline__ u32 pack2bf(float a, float b) {
    __nv_bfloat162 t = __floats2bfloat162_rn(a, b);
    return *reinterpret_cast<u32*>(&t);
}
__device__ __forceinline__ float bf_hi(float x) {
    return __bfloat162float(__float2bfloat16(x));
}

#define LDP 40  // bf16 elements per 32-k row (pad 32 -> 40, conflict-free ldmatrix)

// ---------------- kernel 0: zero row sums ----------------
__global__ void zero_rowsum_kernel() {
    int i = blockIdx.x * blockDim.x + threadIdx.x;
    if (i < BB * PP) g_rowsum[i] = 0.0f;
}

// ---------------- kernel 1: ek / ek*v  ([32768,128] @ [128,256]) FFMA2 ----------------
__global__ void __launch_bounds__(256, 2) kv_kernel(const float* __restrict__ enc,
                                                    const float* __restrict__ Wk,
                                                    const float* __restrict__ Wv) {
    extern __shared__ float sm[];
    float* At  = sm;              // [128][64]
    float* Ws0 = sm + 128 * 64;   // [32][256]
    float* Ws1 = Ws0 + 32 * 256;
    const int tid = threadIdx.x;
    const int r0 = blockIdx.x * 64;

    {
        int r = tid >> 2;
        int c0 = (tid & 3) * 32;
        const float4* e4 = (const float4*)(enc + (size_t)(r0 + r) * 128 + c0);
#pragma unroll
        for (int q = 0; q < 8; q++) {
            float4 v = e4[q];
            int k = c0 + q * 4;
            At[(k + 0) * 64 + r] = v.x;
            At[(k + 1) * 64 + r] = v.y;
            At[(k + 2) * 64 + r] = v.z;
            At[(k + 3) * 64 + r] = v.w;
        }
    }
#define FILL_W(dst, k0)                                                           \
    {                                                                              \
        _Pragma("unroll")                                                          \
        for (int t = 0; t < 8; t++) {                                              \
            int l = tid + 256 * t;                                                 \
            int k = l >> 6, c16 = l & 63;                                          \
            const float* src = (c16 < 32) ? (Wk + ((k0) + k) * 128 + c16 * 4)      \
                                          : (Wv + ((k0) + k) * 128 + (c16 - 32) * 4); \
            cp16((dst) + k * 256 + c16 * 4, src);                                  \
        }                                                                          \
    }
    FILL_W(Ws0, 0);
    cp_commit(); cp_wait0();
    __syncthreads();

    const int rb = (tid >> 5) * 8;
    const int cb = (tid & 31) * 4;
    u64 acc[4][8] = {};

    for (int ch = 0; ch < 4; ch++) {
        float* Wc = (ch & 1) ? Ws1 : Ws0;
        float* Wn = (ch & 1) ? Ws0 : Ws1;
        if (ch < 3) { FILL_W(Wn, (ch + 1) * 32); cp_commit(); }
        int k0 = ch * 32;
#pragma unroll
        for (int k = 0; k < 32; k++) {
            const float* ar = At + (k0 + k) * 64 + rb;
            u64 a0 = *(const u64*)(ar + 0);
            u64 a1 = *(const u64*)(ar + 2);
            u64 a2 = *(const u64*)(ar + 4);
            u64 a3 = *(const u64*)(ar + 6);
            float4 wk4 = *(const float4*)(Wc + k * 256 + cb);
            float4 wv4 = *(const float4*)(Wc + k * 256 + cb + 128);
            float w[8] = {wk4.x, wk4.y, wk4.z, wk4.w, wv4.x, wv4.y, wv4.z, wv4.w};
#pragma unroll
            for (int j = 0; j < 8; j++) {
                u64 wd = dup2(w[j]);
                ffma2(acc[0][j], a0, wd);
                ffma2(acc[1][j], a1, wd);
                ffma2(acc[2][j], a2, wd);
                ffma2(acc[3][j], a3, wd);
            }
        }
        if (ch < 3) cp_wait0();
        __syncthreads();
    }
#undef FILL_W

#pragma unroll
    for (int t = 0; t < 4; t++) {
        int row = r0 + rb + 2 * t;
#pragma unroll
        for (int j = 0; j < 4; j++) {
            float2 pk = unpack2(acc[t][j]);
            float2 pv = unpack2(acc[t][j + 4]);
            int c = cb + j;
            float e0 = fexp(pk.x), e1 = fexp(pk.y);
            g_ekk[(size_t)row * 256 + c]             = e0 * pv.x;
            g_ekk[(size_t)row * 256 + c + 128]       = e0;
            g_ekk[(size_t)(row + 1) * 256 + c]       = e1 * pv.y;
            g_ekk[(size_t)(row + 1) * 256 + c + 128] = e1;
        }
    }
}

// ---------------- kernel 2: sigmoid(q1+q2+q_last) FFMA2 ----------------
__global__ void __launch_bounds__(256, 2) q_kernel(const float* __restrict__ q1,
                                                   const float* __restrict__ q2,
                                                   const float* __restrict__ lastn,
                                                   const float* __restrict__ loadv,
                                                   const float* __restrict__ leftv,
                                                   const float* __restrict__ Wq1,
                                                   const float* __restrict__ Wq2,
                                                   const float* __restrict__ Wql) {
    extern __shared__ float sm[];
    float* At = sm;            // [128][64]
    float* Ws = sm + 128 * 64; // [128][128]
    const int tid = threadIdx.x;
    const int r0 = blockIdx.x * 64;
    const int rb = (tid >> 5) * 8;
    const int cb = (tid & 31) * 4;

    u64 acc[4][4] = {};
    const float* Asrc[3] = {q1, q2, lastn};
    const float* Wsrc[3] = {Wq1, Wq2, Wql};

    for (int ph = 0; ph < 3; ph++) {
        __syncthreads();
        {
            int r = tid >> 2;
            int c0 = (tid & 3) * 32;
            const float4* a4 = (const float4*)(Asrc[ph] + (size_t)(r0 + r) * 128 + c0);
#pragma unroll
            for (int q = 0; q < 8; q++) {
                float4 v = a4[q];
                int k = c0 + q * 4;
                At[(k + 0) * 64 + r] = v.x;
                At[(k + 1) * 64 + r] = v.y;
                At[(k + 2) * 64 + r] = v.z;
                At[(k + 3) * 64 + r] = v.w;
            }
            const float4* W4 = (const float4*)Wsrc[ph];
            float4* Ws4 = (float4*)Ws;
            for (int i = tid; i < 128 * 32; i += 256) Ws4[i] = W4[i];
        }
        __syncthreads();
#pragma unroll 8
        for (int k = 0; k < 128; k++) {
            const float* ar = At + k * 64 + rb;
            u64 a0 = *(const u64*)(ar + 0);
            u64 a1 = *(const u64*)(ar + 2);
            u64 a2 = *(const u64*)(ar + 4);
            u64 a3 = *(const u64*)(ar + 6);
            float4 w4 = *(const float4*)(Ws + k * 128 + cb);
            float w[4] = {w4.x, w4.y, w4.z, w4.w};
#pragma unroll
            for (int j = 0; j < 4; j++) {
                u64 wd = dup2(w[j]);
                ffma2(acc[0][j], a0, wd);
                ffma2(acc[1][j], a1, wd);
                ffma2(acc[2][j], a2, wd);
                ffma2(acc[3][j], a3, wd);
            }
        }
    }

#pragma unroll
    for (int t = 0; t < 4; t++) {
        int row = r0 + rb + 2 * t;
        float lo0 = loadv[row], le0 = leftv[row];
        float lo1 = loadv[row + 1], le1 = leftv[row + 1];
#pragma unroll
        for (int j = 0; j < 4; j++) {
            int c = cb + j;
            float2 p = unpack2(acc[t][j]);
            float wl = Wql[128 * 128 + c];
            float we = Wql[129 * 128 + c];
            float v0 = p.x + lo0 * wl + le0 * we;
            float v1 = p.y + lo1 * wl + le1 * we;
            g_sigq[(size_t)row * 128 + c]       = 1.0f / (1.0f + fexp(-v0));
            g_sigq[(size_t)(row + 1) * 128 + c] = 1.0f / (1.0f + fexp(-v1));
        }
    }
}

// ---------------- kernel 3: transpose+split g_ekk -> ekkT hi/lo ----------------
__global__ void ekkT_split_kernel() {
    __shared__ float t[32][33];
    const int n0 = blockIdx.x * 32;
    const int c0 = blockIdx.y * 32;
    const int b = blockIdx.z;
    const int tx = threadIdx.x, ty = threadIdx.y;
#pragma unroll
    for (int i = 0; i < 4; i++)
        t[ty + i * 8][tx] = g_ekk[(size_t)(b * NN + n0 + ty + i * 8) * 256 + c0 + tx];
    __syncthreads();
#pragma unroll
    for (int i = 0; i < 4; i++) {
        int c = c0 + ty + i * 8;
        float v = t[tx][ty + i * 8];
        float h = bf_hi(v);
        size_t o = (size_t)(b * 256 + c) * NN + n0 + tx;
        g_ekkT_h[o] = __float2bfloat16(h);
        g_ekkT_l[o] = __float2bfloat16(v - h);
    }
}

// ---------------- kernel 4: b GEMM via bf16x3 mma ----------------
// per batch: C[p 1024][c 256] = sum_n exp(nf-c1*cd)[p][n] * ekkT[c][n]
// grid (16, 32): block tile M=64 (p), N=256 (c), K=1024 chunked by 32. 256 thr.
__global__ void __launch_bounds__(256, 2) b_mma_kernel(const float* __restrict__ cur,
                                                       const float* __restrict__ ninf,
                                                       const float* __restrict__ lsp,
                                                       const float* __restrict__ aalpha) {
    extern __shared__ __nv_bfloat16 sb[];
    // stage layout (bf16 units): Ah[64*40]=2560, Al=2560, Bh[256*40]=10240, Bl=10240
    const int SSTG = 25600;
    const int tid = threadIdx.x;
    const int b = blockIdx.y;
    const int p0 = blockIdx.x * 64;
    const float c1 = lsp[0] * aalpha[0];

    const int lane = tid & 31;
    const int wid = tid >> 5;
    const int wm = wid >> 2;   // 0..1  rows wm*32
    const int wn = wid & 3;    // cols wn*64

    // A prefetch regs
    const int rA = tid >> 2;          // 0..63
    const int kqA = (tid & 3) * 8;
    const float4* cur4 = (const float4*)cur;
    const float4* ninf4 = (const float4*)ninf;
    const size_t arow4 = (size_t)(b * PP + p0 + rA) * 256;
    float4 cd0, cd1, nf0, nf1;

#define LD_A(k0)                                \
    {                                           \
        size_t gi = arow4 + ((k0) + kqA) / 4;   \
        cd0 = cur4[gi]; cd1 = cur4[gi + 1];     \
        nf0 = ninf4[gi]; nf1 = ninf4[gi + 1];   \
    }
#define ST_A(st)                                                                  \
    {                                                                             \
        float e[8];                                                               \
        e[0] = fexp(nf0.x - c1 * cd0.x); e[1] = fexp(nf0.y - c1 * cd0.y);         \
        e[2] = fexp(nf0.z - c1 * cd0.z); e[3] = fexp(nf0.w - c1 * cd0.w);         \
        e[4] = fexp(nf1.x - c1 * cd1.x); e[5] = fexp(nf1.y - c1 * cd1.y);         \
        e[6] = fexp(nf1.z - c1 * cd1.z); e[7] = fexp(nf1.w - c1 * cd1.w);         \
        float h[8], l[8];                                                         \
        _Pragma("unroll")                                                         \
        for (int j = 0; j < 8; j++) { h[j] = bf_hi(e[j]); l[j] = e[j] - h[j]; }   \
        uint4 hv = make_uint4(pack2bf(h[0], h[1]), pack2bf(h[2], h[3]),           \
                              pack2bf(h[4], h[5]), pack2bf(h[6], h[7]));          \
        uint4 lv = make_uint4(pack2bf(l[0], l[1]), pack2bf(l[2], l[3]),           \
                              pack2bf(l[4], l[5]), pack2bf(l[6], l[7]));          \
        *(uint4*)(sb + (st) * SSTG + rA * LDP + kqA)        = hv;                 \
        *(uint4*)(sb + (st) * SSTG + 2560 + rA * LDP + kqA) = lv;                 \
    }
#define FILL_B(st, k0)                                                            \
    {                                                                             \
        _Pragma("unroll")                                                         \
        for (int t = 0; t < 8; t++) {                                             \
            int idx = tid + 256 * t;                                              \
            int kind = idx >> 10;                                                 \
            int r = (idx >> 2) & 255;                                             \
            int c16 = idx & 3;                                                    \
            const __nv_bfloat16* src = (kind ? g_ekkT_l : g_ekkT_h) +             \
                (size_t)(b * 256 + r) * NN + (k0) + c16 * 8;                      \
            cp16(sb + (st) * SSTG + 5120 + kind * 10240 + r * LDP + c16 * 8, src);\
        }                                                                         \
    }

    LD_A(0); ST_A(0);
    FILL_B(0, 0);
    cp_commit(); cp_wait0();
    __syncthreads();

    float C[2][8][4];
#pragma unroll
    for (int mt = 0; mt < 2; mt++)
#pragma unroll
        for (int nt = 0; nt < 8; nt++)
#pragma unroll
            for (int i = 0; i < 4; i++) C[mt][nt][i] = 0.0f;

    for (int ch = 0; ch < 32; ch++) {
        int st = ch & 1;
        int ns = st ^ 1;
        if (ch < 31) { LD_A((ch + 1) * 32); FILL_B(ns, (ch + 1) * 32); cp_commit(); }

        u32 uAh = smem_u32(sb + st * SSTG);
        u32 uAl = uAh + 2560 * 2;
        u32 uBh = uAh + 5120 * 2;
        u32 uBl = uAh + 15360 * 2;

#pragma unroll
        for (int half = 0; half < 2; half++) {
            int k16 = half * 16;
            u32 bh[8][2], bl[8][2];
#pragma unroll
            for (int ntp = 0; ntp < 4; ntp++) {
                int brow = wn * 64 + ntp * 16 + (lane & 7) + ((lane >> 4) << 3);
                u32 boff = (u32)(brow * LDP + k16 + (((lane >> 3) & 1) << 3)) * 2;
                u32 r0, r1, r2, r3;
                ldsm_x4(uBh + boff, r0, r1, r2, r3);
                bh[2 * ntp][0] = r0; bh[2 * ntp][1] = r1;
                bh[2 * ntp + 1][0] = r2; bh[2 * ntp + 1][1] = r3;
                ldsm_x4(uBl + boff, r0, r1, r2, r3);
                bl[2 * ntp][0] = r0; bl[2 * ntp][1] = r1;
                bl[2 * ntp + 1][0] = r2; bl[2 * ntp + 1][1] = r3;
            }
#pragma unroll
            for (int mt = 0; mt < 2; mt++) {
                int arow = wm * 32 + mt * 16 + (lane & 15);
                u32 aoff = (u32)(arow * LDP + k16 + ((lane >> 4) << 3)) * 2;
                u32 ah[4], al[4];
                ldsm_x4(uAh + aoff, ah[0], ah[1], ah[2], ah[3]);
                ldsm_x4(uAl + aoff, al[0], al[1], al[2], al[3]);
#pragma unroll
                for (int nt = 0; nt < 8; nt++) {
                    mma_bf16(C[mt][nt], ah, bh[nt]);
                    mma_bf16(C[mt][nt], ah, bl[nt]);
                    mma_bf16(C[mt][nt], al, bh[nt]);
                }
            }
        }
        if (ch < 31) { ST_A(ns); cp_wait0(); }
        __syncthreads();
    }
#undef LD_A
#undef ST_A
#undef FILL_B

#pragma unroll
    for (int mt = 0; mt < 2; mt++) {
#pragma unroll
        for (int nt = 0; nt < 8; nt++) {
            int r = p0 + wm * 32 + mt * 16 + (lane >> 2);
            int col = wn * 64 + nt * 8 + ((lane & 3) << 1);
            size_t o = (size_t)(b * PP + r) * 256 + col;
            *(float2*)(g_numden + o) = make_float2(C[mt][nt][0], C[mt][nt][1]);
            *(float2*)(g_numden + o + 8 * 256) = make_float2(C[mt][nt][2], C[mt][nt][3]);
        }
    }
}

// ---------------- kernel 5: aft split (sigq*num/den -> bf16 hi/lo) ----------------
__global__ void aft_split_kernel() {
    int idx = blockIdx.x * blockDim.x + threadIdx.x;  // float4 index over [32768][32]
    int row = idx >> 5, dq = idx & 31;
    const float4* nd4 = (const float4*)g_numden;
    const float4* sq4 = (const float4*)g_sigq;
    float4 num = nd4[(size_t)row * 64 + dq];
    float4 den = nd4[(size_t)row * 64 + 32 + dq];
    float4 sq = sq4[(size_t)row * 32 + dq];
    float v[4];
    v[0] = sq.x * num.x / (den.x + 1e-20f);
    v[1] = sq.y * num.y / (den.y + 1e-20f);
    v[2] = sq.z * num.z / (den.z + 1e-20f);
    v[3] = sq.w * num.w / (den.w + 1e-20f);
    float h[4];
#pragma unroll
    for (int j = 0; j < 4; j++) h[j] = bf_hi(v[j]);
    size_t o = (size_t)row * 128 + dq * 4;
    *(uint2*)(g_aft_h + o) = make_uint2(pack2bf(h[0], h[1]), pack2bf(h[2], h[3]));
    *(uint2*)(g_aft_l + o) = make_uint2(pack2bf(v[0] - h[0], v[1] - h[1]),
                                        pack2bf(v[2] - h[2], v[3] - h[3]));
}

// ---------------- kernel 6: enc split ----------------
__global__ void enc_split_kernel(const float* __restrict__ enc) {
    int idx = blockIdx.x * blockDim.x + threadIdx.x;  // float4 index
    float4 v = ((const float4*)enc)[idx];
    float h0 = bf_hi(v.x), h1 = bf_hi(v.y), h2 = bf_hi(v.z), h3 = bf_hi(v.w);
    size_t o = (size_t)idx * 4;
    *(uint2*)(g_enc_h + o) = make_uint2(pack2bf(h0, h1), pack2bf(h2, h3));
    *(uint2*)(g_enc_l + o) = make_uint2(pack2bf(v.x - h0, v.y - h1),
                                        pack2bf(v.z - h2, v.w - h3));
}

// ---------------- kernel 7: c GEMM via bf16x3 mma + fused epilogue ----------------
// per batch: S[p][n] = sum_d aft[p][d]*enc[n][d]; epilogue tanh/exp/rowsum.
// grid (8, 8, 32): tile 128(p) x 128(n), K=128 chunked by 32. 256 thr.
__global__ void __launch_bounds__(256, 2) c_mma_kernel(const float* __restrict__ cur,
                                                       const float* __restrict__ ninf,
                                                       const float* __restrict__ lsp,
                                                       const float* __restrict__ palpha,
                                                       float* __restrict__ out) {
    extern __shared__ __nv_bfloat16 sb[];
    // stage (bf16 units): Ah[128*40]=5120, Al=5120, Bh=5120, Bl=5120 -> 20480
    const int SSTG = 20480;
    const int tid = threadIdx.x;
    const int p0 = blockIdx.x * 128;
    const int n0 = blockIdx.y * 128;
    const int b = blockIdx.z;
    const int lane = tid & 31;
    const int wid = tid >> 5;
    const int wm = wid >> 2;  // 0..1 rows wm*64
    const int wn = wid & 3;   // cols wn*32

#define FILL_C(st, k0)                                                             \
    {                                                                              \
        _Pragma("unroll")                                                          \
        for (int t = 0; t < 8; t++) {                                              \
            int idx = tid + 256 * t;                                               \
            int opnd = idx >> 10;                                                  \
            int j = idx & 1023;                                                    \
            int kind = j >> 9;                                                     \
            int r = (j >> 2) & 127;                                                \
            int c16 = j & 3;                                                       \
            const __nv_bfloat16* src;                                              \
            if (opnd == 0)                                                         \
                src = (kind ? g_aft_l : g_aft_h) +                                 \
                      (size_t)(b * PP + p0 + r) * 128 + (k0) + c16 * 8;            \
            else                                                                   \
                src = (kind ? g_enc_l : g_enc_h) +                                 \
                      (size_t)(b * NN + n0 + r) * 128 + (k0) + c16 * 8;            \
            cp16(sb + (st) * SSTG + opnd * 10240 + kind * 5120 + r * LDP + c16 * 8, src); \
        }                                                                          \
    }

    FILL_C(0, 0);
    cp_commit(); cp_wait0();
    __syncthreads();

    float C[4][4][4];
#pragma unroll
    for (int mt = 0; mt < 4; mt++)
#pragma unroll
        for (int nt = 0; nt < 4; nt++)
#pragma unroll
            for (int i = 0; i < 4; i++) C[mt][nt][i] = 0.0f;

    for (int ch = 0; ch < 4; ch++) {
        int st = ch & 1;
        int ns = st ^ 1;
        if (ch < 3) { FILL_C(ns, (ch + 1) * 32); cp_commit(); }

        u32 uAh = smem_u32(sb + st * SSTG);
        u32 uAl = uAh + 5120 * 2;
        u32 uBh = uAh + 10240 * 2;
        u32 uBl = uAh + 15360 * 2;

#pragma unroll
        for (int half = 0; half < 2; half++) {
            int k16 = half * 16;
            u32 bh[4][2], bl[4][2];
#pragma unroll
            for (int ntp = 0; ntp < 2; ntp++) {
                int brow = wn * 32 + ntp * 16 + (lane & 7) + ((lane >> 4) << 3);
                u32 boff = (u32)(brow * LDP + k16 + (((lane >> 3) & 1) << 3)) * 2;
                u32 r0, r1, r2, r3;
                ldsm_x4(uBh + boff, r0, r1, r2, r3);
                bh[2 * ntp][0] = r0; bh[2 * ntp][1] = r1;
                bh[2 * ntp + 1][0] = r2; bh[2 * ntp + 1][1] = r3;
                ldsm_x4(uBl + boff, r0, r1, r2, r3);
                bl[2 * ntp][0] = r0; bl[2 * ntp][1] = r1;
                bl[2 * ntp + 1][0] = r2; bl[2 * ntp + 1][1] = r3;
            }
#pragma unroll
            for (int mt = 0; mt < 4; mt++) {
                int arow = wm * 64 + mt * 16 + (lane & 15);
                u32 aoff = (u32)(arow * LDP + k16 + ((lane >> 4) << 3)) * 2;
                u32 ah[4], al[4];
                ldsm_x4(uAh + aoff, ah[0], ah[1], ah[2], ah[3]);
                ldsm_x4(uAl + aoff, al[0], al[1], al[2], al[3]);
#pragma unroll
                for (int nt = 0; nt < 4; nt++) {
                    mma_bf16(C[mt][nt], ah, bh[nt]);
                    mma_bf16(C[mt][nt], ah, bl[nt]);
                    mma_bf16(C[mt][nt], al, bh[nt]);
                }
            }
        }
        if (ch < 3) cp_wait0();
        __syncthreads();
    }
#undef FILL_C

    // epilogue
    const float c2 = lsp[0] * palpha[0];
    const float inv_sqrt_e = 1.0f / 11.313708498984761f;
#pragma unroll
    for (int mt = 0; mt < 4; mt++) {
#pragma unroll
        for (int h2 = 0; h2 < 2; h2++) {
            int prow = p0 + wm * 64 + mt * 16 + (lane >> 2) + h2 * 8;
            float part = 0.0f;
#pragma unroll
            for (int nt = 0; nt < 4; nt++) {
                int coln = n0 + wn * 32 + nt * 8 + ((lane & 3) << 1);
                size_t gi = (size_t)(b * PP + prow) * NN + coln;
                float2 cdv = *(const float2*)(cur + gi);
                float2 nfv = *(const float2*)(ninf + gi);
                float s0 = C[mt][nt][h2 * 2 + 0] * inv_sqrt_e - c2 * cdv.x;
                float s1 = C[mt][nt][h2 * 2 + 1] * inv_sqrt_e - c2 * cdv.y;
                float e0 = fexp(10.0f * ftanh(s0) + nfv.x - 10.0f);
                float e1 = fexp(10.0f * ftanh(s1) + nfv.y - 10.0f);
                *(float2*)(out + gi) = make_float2(e0, e1);
                part += e0 + e1;
            }
            part += __shfl_xor_sync(0xffffffffu, part, 2);
            part += __shfl_xor_sync(0xffffffffu, part, 1);
            if ((lane & 3) == 0) atomicAdd(&g_rowsum[b * PP + prow], part);
        }
    }
}

// ---------------- kernel 8: normalize ----------------
__global__ void norm_kernel(float* __restrict__ out) {
    int i = blockIdx.x * blockDim.x + threadIdx.x;  // float4 index
    float4* o4 = (float4*)out;
    float4 v = o4[i];
    float inv = 1.0f / g_rowsum[i >> 8];
    v.x *= inv; v.y *= inv; v.z *= inv; v.w *= inv;
    o4[i] = v;
}

// ---------------- launch ----------------
extern "C" void kernel_launch(void* const* d_in, const int* in_sizes, int n_in,
                              void* d_out, int out_size) {
    (void)in_sizes; (void)n_in; (void)out_size;
    const float* enc    = (const float*)d_in[0];
    const float* q1     = (const float*)d_in[1];
    const float* q2     = (const float*)d_in[2];
    const float* lastn  = (const float*)d_in[3];
    const float* loadv  = (const float*)d_in[4];
    const float* leftv  = (const float*)d_in[5];
    const float* cur    = (const float*)d_in[6];
    const float* ls     = (const float*)d_in[7];
    const float* ninf   = (const float*)d_in[8];
    const float* Wq1    = (const float*)d_in[9];
    const float* Wq2    = (const float*)d_in[10];
    const float* Wql    = (const float*)d_in[11];
    const float* Wk     = (const float*)d_in[12];
    const float* Wv     = (const float*)d_in[13];
    const float* aalpha = (const float*)d_in[14];
    const float* palpha = (const float*)d_in[15];
    float* out = (float*)d_out;

    cudaFuncSetAttribute(kv_kernel, cudaFuncAttributeMaxDynamicSharedMemorySize, 98304);
    cudaFuncSetAttribute(q_kernel, cudaFuncAttributeMaxDynamicSharedMemorySize, 98304);
    cudaFuncSetAttribute(b_mma_kernel, cudaFuncAttributeMaxDynamicSharedMemorySize, 102400);
    cudaFuncSetAttribute(c_mma_kernel, cudaFuncAttributeMaxDynamicSharedMemorySize, 81920);

    zero_rowsum_kernel<<<32, 1024>>>();
    kv_kernel<<<512, 256, 98304>>>(enc, Wk, Wv);
    enc_split_kernel<<<4096, 256>>>(enc);
    ekkT_split_kernel<<<dim3(32, 8, 32), dim3(32, 8)>>>();
    q_kernel<<<512, 256, 98304>>>(q1, q2, lastn, loadv, leftv, Wq1, Wq2, Wql);
    b_mma_kernel<<<dim3(16, 32), 256, 102400>>>(cur, ninf, ls, aalpha);
    aft_split_kernel<<<4096, 256>>>();
    c_mma_kernel<<<dim3(8, 8, 32), 256, 81920>>>(cur, ninf, ls, palpha, out);
    norm_kernel<<<32768, 256>>>(out);
}